// round 16
// baseline (speedup 1.0000x reference)
#include <cuda_runtime.h>
#include <math.h>
#include <stdint.h>

// ---------------- dimensions ----------------
#define NB   32
#define C0   2
#define H0   400
#define W0   600
#define KH1  10
#define KW1  11
#define H1   50
#define W1   66
#define OC1  64
#define POS1 (NB*H1*W1)          // 105600
#define K1   (KH1*KW1*C0)        // 220
#define H2   5
#define W2   6
#define POS2 (NB*H2*W2)          // 960
#define K2   (12*12*64)          // 9216
#define KE   512
#define TH   50
#define TW   60
#define POSD (NB*TH*TW)          // 96000
#define NT1  (12*12*64)          // 9216
#define NT2  (10*11*2)           // 220
#define OHH  400
#define OWW  540
#define RECON_N (NB*2*OHH*OWW)   // 13824000

// ---------------- f32x2 packed FMA (sm_103a) ----------------
#define PACK2(d, lo, hi) asm("mov.b64 %0, {%1, %2};" : "=l"(d) : "f"(lo), "f"(hi))
#define UNPACK2(lo, hi, d) asm("mov.b64 {%0, %1}, %2;" : "=f"(lo), "=f"(hi) : "l"(d))
#define FMA2(d, a, b) asm("fma.rn.f32x2 %0, %1, %2, %0;" : "+l"(d) : "l"(a), "l"(b))

// ---------------- scratch ----------------
__device__ float g_A1  [(size_t)POS1*K1];
__device__ float g_h1  [(size_t)POS1*OC1];
__device__ float g_col [(size_t)POS2*K2];
__device__ float g_hA  [POS2*128];
__device__ float g_hB  [POS2*128];
__device__ float g_t64 [POS2*64];
__device__ float g_z   [POS2*64];
__device__ float g_q   [POS2*64];
__device__ float g_part[16*POS2*128];
__device__ float g_Y1  [(size_t)POS2*NT1];
__device__ float g_t1  [(size_t)POSD*64];
__device__ float g_Y2  [(size_t)POSD*NT2];
__device__ float g_w1t [K1*OC1];
__device__ float g_w2t [K2*128];
__device__ float g_w3t [9*128*128];
__device__ float g_er1t[2*9*128*64];
__device__ float g_er2t[2*64*128];
__device__ float g_pret[128*64];
__device__ float g_d1t [9*64*128];
__device__ float g_dr1t[2*9*128*64];
__device__ float g_dr2t[2*64*128];
__device__ float g_tw1t[128*NT1];
__device__ float g_tw2t[64*NT2];
__device__ float g_esq [KE];
__device__ int   g_counts[KE];
__device__ float g_sqacc[1];
__device__ int   g_idx [POS2];

// ---------------- merged weight transpose ----------------
#define NJOBS 15
struct TJobs {
    const float* src[NJOBS];
    float*       dst[NJOBS];
    int cout[NJOBS], cin[NJOBS], kh[NJOBS], kw[NJOBS], isT[NJOBS];
    long off[NJOBS+1];
};

__global__ void wtrans_all_kernel(TJobs J) {
    long t = (long)blockIdx.x * blockDim.x + threadIdx.x;
    if (t >= J.off[NJOBS]) return;
    int j = 0;
#pragma unroll
    for (int i = 0; i < NJOBS-1; i++) j += (t >= J.off[i+1]) ? 1 : 0;
    long u = t - J.off[j];
    int Cout = J.cout[j], Cin = J.cin[j], KH = J.kh[j], KW = J.kw[j];
    int oc = (int)(u % Cout); long r = u / Cout;
    if (!J.isT[j]) {
        int ic = (int)(r % Cin);
        int kk = (int)(r / Cin);
        int khh = kk / KW, kww = kk % KW;
        J.dst[j][u] = J.src[j][((oc*Cin + ic)*KH + khh)*KW + kww];
    } else {
        int khw = KH*KW;
        int kk = (int)(r % khw);
        int ic = (int)(r / khw);
        J.dst[j][u] = J.src[j][(ic*Cout + oc)*khw + kk];
    }
}

// ---------------- conv1 im2col: NCHW in, C0=2, float2 store ----------------
__global__ void im2col_c1_kernel(const float* __restrict__ in, float* __restrict__ out) {
    const int total2 = POS1 * (K1/2);
    int t = blockIdx.x * blockDim.x + threadIdx.x;
    if (t >= total2) return;
    int k2  = t % 110;
    int pos = t / 110;
    int kw = k2 % 11;
    int kh = k2 / 11;
    int ow = pos % W1;
    int r2 = pos / W1;
    int oh = r2 % H1;
    int b  = r2 / H1;
    int ih = oh*8 - 1 + kh;
    int iw = ow*9 - 1 + kw;
    float v0 = 0.f, v1 = 0.f;
    if (ih >= 0 && ih < H0 && iw >= 0 && iw < W0) {
        long base = (((long)b*2)*H0 + ih)*W0 + iw;
        v0 = in[base];
        v1 = in[base + (long)H0*W0];
    }
    *(float2*)(out + (size_t)t*2) = make_float2(v0, v1);
}

// ---------------- conv2 explicit im2col (4 ch/thread, float4) ----------------
__global__ void im2col4_c2_kernel(const float* __restrict__ in, float* __restrict__ out) {
    const int total4 = POS2 * 12*12*16;
    int t = blockIdx.x * blockDim.x + threadIdx.x;
    if (t >= total4) return;
    const int KC4 = 12*12*16;
    int k4  = t % KC4;
    int pos = t / KC4;
    int ic = (k4 & 15) * 4;
    int r  = k4 >> 4;
    int kw = r % 12;
    int kh = r / 12;
    int ow = pos % W2;
    int r2 = pos / W2;
    int oh = r2 % H2;
    int b  = r2 / H2;
    int ih = oh*10 - 1 + kh;
    int iw = ow*10 - 1 + kw;
    float4 v = make_float4(0.f, 0.f, 0.f, 0.f);
    if (ih >= 0 && ih < H1 && iw >= 0 && iw < W1)
        v = *(const float4*)(in + (((long)(b*H1 + ih))*W1 + iw)*64 + ic);
    *(float4*)(out + (size_t)t*4) = v;
}

// ---------------- tf32 helpers ----------------
__device__ __forceinline__ uint32_t f2tf32(float x) {
    uint32_t r;
    asm("cvt.rna.tf32.f32 %0, %1;" : "=r"(r) : "f"(x));
    return r;
}
__device__ __forceinline__ void split3(float v, uint32_t& hi, uint32_t& lo) {
    hi = f2tf32(v);
    lo = f2tf32(v - __uint_as_float(hi));
}
#define MMA_TF32(acc, a0,a1,a2,a3, b0,b1) \
    asm volatile( \
        "mma.sync.aligned.m16n8k8.row.col.f32.tf32.tf32.f32 " \
        "{%0,%1,%2,%3}, {%4,%5,%6,%7}, {%8,%9}, {%0,%1,%2,%3};" \
        : "+f"((acc)[0]), "+f"((acc)[1]), "+f"((acc)[2]), "+f"((acc)[3]) \
        : "r"(a0), "r"(a1), "r"(a2), "r"(a3), "r"(b0), "r"(b1))

// ---------------- 3xTF32 GEMM (fp32-accurate, tensor cores; split-K, explicit A) ----------------
__global__ __launch_bounds__(256)
void gemm3x_kernel(const float* __restrict__ A, const float* __restrict__ B,
                   float* __restrict__ Cpart, int M, int N, int K, int Kc)
{
    __shared__ float As[128][17];
    __shared__ float Bs[16][72];
    int m0 = blockIdx.y * 128;
    int n0 = blockIdx.x * 64;
    int s  = blockIdx.z;
    int kbeg = s * Kc;
    int kend = kbeg + Kc; if (kend > K) kend = K;
    int tid = threadIdx.x;
    int warp = tid >> 5, lane = tid & 31;
    int wm = warp >> 1, wn = warp & 1;
    int g = lane >> 2, tg = lane & 3;

    float acc[2][4][4];
#pragma unroll
    for (int mi = 0; mi < 2; mi++)
#pragma unroll
        for (int ni = 0; ni < 4; ni++)
#pragma unroll
            for (int c = 0; c < 4; c++) acc[mi][ni][c] = 0.f;

    for (int k0 = kbeg; k0 < kend; k0 += 16) {
#pragma unroll
        for (int r = 0; r < 8; r++) {
            int t = tid + r*256;
            int m = t >> 4, k = t & 15;
            int gm = m0 + m, gk = k0 + k;
            As[m][k] = (gm < M && gk < kend) ? A[(size_t)gm*K + gk] : 0.f;
        }
#pragma unroll
        for (int r = 0; r < 4; r++) {
            int t = tid + r*256;
            int k = t >> 6, n = t & 63;
            int gk = k0 + k, gn = n0 + n;
            Bs[k][n] = (gk < kend && gn < N) ? B[(size_t)gk*N + gn] : 0.f;
        }
        __syncthreads();
#pragma unroll
        for (int kk = 0; kk < 16; kk += 8) {
            uint32_t ah[2][4], al[2][4], bh[4][2], bl[4][2];
#pragma unroll
            for (int mi = 0; mi < 2; mi++) {
                int mrow = wm*32 + mi*16;
                split3(As[mrow + g    ][kk + tg    ], ah[mi][0], al[mi][0]);
                split3(As[mrow + g + 8][kk + tg    ], ah[mi][1], al[mi][1]);
                split3(As[mrow + g    ][kk + tg + 4], ah[mi][2], al[mi][2]);
                split3(As[mrow + g + 8][kk + tg + 4], ah[mi][3], al[mi][3]);
            }
#pragma unroll
            for (int ni = 0; ni < 4; ni++) {
                int ncol = wn*32 + ni*8 + g;
                split3(Bs[kk + tg    ][ncol], bh[ni][0], bl[ni][0]);
                split3(Bs[kk + tg + 4][ncol], bh[ni][1], bl[ni][1]);
            }
#pragma unroll
            for (int mi = 0; mi < 2; mi++)
#pragma unroll
                for (int ni = 0; ni < 4; ni++) {
                    MMA_TF32(acc[mi][ni], ah[mi][0],ah[mi][1],ah[mi][2],ah[mi][3], bl[ni][0],bl[ni][1]);
                    MMA_TF32(acc[mi][ni], al[mi][0],al[mi][1],al[mi][2],al[mi][3], bh[ni][0],bh[ni][1]);
                    MMA_TF32(acc[mi][ni], ah[mi][0],ah[mi][1],ah[mi][2],ah[mi][3], bh[ni][0],bh[ni][1]);
                }
        }
        __syncthreads();
    }
    float* Cs = Cpart + (size_t)s*M*N;
#pragma unroll
    for (int mi = 0; mi < 2; mi++) {
#pragma unroll
        for (int ni = 0; ni < 4; ni++) {
            int gmA = m0 + wm*32 + mi*16 + g;
            int gmB = gmA + 8;
            int gn0 = n0 + wn*32 + ni*8 + 2*tg;
            if (gmA < M) {
                if (gn0     < N) Cs[(size_t)gmA*N + gn0    ] = acc[mi][ni][0];
                if (gn0 + 1 < N) Cs[(size_t)gmA*N + gn0 + 1] = acc[mi][ni][1];
            }
            if (gmB < M) {
                if (gn0     < N) Cs[(size_t)gmB*N + gn0    ] = acc[mi][ni][2];
                if (gn0 + 1 < N) Cs[(size_t)gmB*N + gn0 + 1] = acc[mi][ni][3];
            }
        }
    }
}

// ---------------- plain tf32 GEMM (decoder only) ----------------
__global__ __launch_bounds__(256)
void gemm_tf32_kernel(const float* __restrict__ A, const float* __restrict__ B,
                      float* __restrict__ C, int M, int N, int K, int reluA)
{
    __shared__ uint32_t As[128][17];
    __shared__ uint32_t Bs[16][72];
    int m0 = blockIdx.y * 128;
    int n0 = blockIdx.x * 64;
    int tid = threadIdx.x;
    int warp = tid >> 5, lane = tid & 31;
    int wm = warp >> 1, wn = warp & 1;
    int groupID = lane >> 2, tig = lane & 3;

    float acc[2][4][4];
#pragma unroll
    for (int mi = 0; mi < 2; mi++)
#pragma unroll
        for (int ni = 0; ni < 4; ni++)
#pragma unroll
            for (int c = 0; c < 4; c++) acc[mi][ni][c] = 0.f;

    for (int k0 = 0; k0 < K; k0 += 16) {
#pragma unroll
        for (int r = 0; r < 8; r++) {
            int t = tid + r*256;
            int m = t >> 4, k = t & 15;
            int gm = m0 + m, gk = k0 + k;
            float v = (gm < M && gk < K) ? A[(size_t)gm*K + gk] : 0.f;
            if (reluA) v = fmaxf(v, 0.f);
            As[m][k] = f2tf32(v);
        }
#pragma unroll
        for (int r = 0; r < 4; r++) {
            int t = tid + r*256;
            int k = t >> 6, n = t & 63;
            int gk = k0 + k, gn = n0 + n;
            float v = (gk < K && gn < N) ? B[(size_t)gk*N + gn] : 0.f;
            Bs[k][n] = f2tf32(v);
        }
        __syncthreads();
#pragma unroll
        for (int kk = 0; kk < 16; kk += 8) {
            uint32_t a[2][4], b[4][2];
#pragma unroll
            for (int mi = 0; mi < 2; mi++) {
                int mrow = wm*32 + mi*16;
                a[mi][0] = As[mrow + groupID    ][kk + tig    ];
                a[mi][1] = As[mrow + groupID + 8][kk + tig    ];
                a[mi][2] = As[mrow + groupID    ][kk + tig + 4];
                a[mi][3] = As[mrow + groupID + 8][kk + tig + 4];
            }
#pragma unroll
            for (int ni = 0; ni < 4; ni++) {
                int ncol = wn*32 + ni*8 + groupID;
                b[ni][0] = Bs[kk + tig    ][ncol];
                b[ni][1] = Bs[kk + tig + 4][ncol];
            }
#pragma unroll
            for (int mi = 0; mi < 2; mi++)
#pragma unroll
                for (int ni = 0; ni < 4; ni++)
                    MMA_TF32(acc[mi][ni], a[mi][0],a[mi][1],a[mi][2],a[mi][3], b[ni][0],b[ni][1]);
        }
        __syncthreads();
    }
#pragma unroll
    for (int mi = 0; mi < 2; mi++) {
#pragma unroll
        for (int ni = 0; ni < 4; ni++) {
            int gmA = m0 + wm*32 + mi*16 + groupID;
            int gmB = gmA + 8;
            int gn0 = n0 + wn*32 + ni*8 + 2*tig;
            if (gmA < M) {
                if (gn0     < N) C[(size_t)gmA*N + gn0    ] = acc[mi][ni][0];
                if (gn0 + 1 < N) C[(size_t)gmA*N + gn0 + 1] = acc[mi][ni][1];
            }
            if (gmB < M) {
                if (gn0     < N) C[(size_t)gmB*N + gn0    ] = acc[mi][ni][2];
                if (gn0 + 1 < N) C[(size_t)gmB*N + gn0 + 1] = acc[mi][ni][3];
            }
        }
    }
}

// ---------------- gemm128 (conv1): 128x64 tile, 8x8 micro, pre-packed FFMA2 ----------------
__global__ __launch_bounds__(128)
void gemm128_kernel(const float* __restrict__ A, const float* __restrict__ B,
                    float* __restrict__ C, int M, int N, int K,
                    const float* __restrict__ bias, int reluOut, int reluA)
{
    __shared__ unsigned long long As2[16][133];  // [k][m], duplicated pair (v,v)
    __shared__ unsigned long long Bs2[16][34];   // [k][n/2], packed adjacent-n pair
    int m0 = blockIdx.y * 128;
    int n0 = blockIdx.x * 64;
    int tid = threadIdx.x;
    int tym = tid >> 3;   // 0..15 -> m = tym*8 + i
    int txn = tid & 7;    // 0..7  -> n pairs txn*4 .. txn*4+3 (n = txn*8..txn*8+7)
    unsigned long long acc2[8][4];
#pragma unroll
    for (int i = 0; i < 8; i++)
#pragma unroll
        for (int j = 0; j < 4; j++) acc2[i][j] = 0ULL;

    for (int k0 = 0; k0 < K; k0 += 16) {
        // A tile 128x16: pack once at load
#pragma unroll
        for (int r = 0; r < 16; r++) {
            int t = tid + r*128;
            int m = t >> 4, k = t & 15;
            int gm = m0 + m, gk = k0 + k;
            float v = (gm < M && gk < K) ? A[(size_t)gm*K + gk] : 0.f;
            if (reluA) v = fmaxf(v, 0.f);
            unsigned long long p;
            PACK2(p, v, v);
            As2[k][m] = p;
        }
        // B tile 16x64 -> 16x32 pairs; coalesced float2 global loads
        {
            int n2 = tid & 31;          // pair index 0..31
            int kb = tid >> 5;          // 0..3
#pragma unroll
            for (int r = 0; r < 4; r++) {
                int k = kb + r*4;
                int gk = k0 + k;
                int gn = n0 + n2*2;
                float x0 = 0.f, x1 = 0.f;
                if (gk < K) {
                    if (gn     < N) x0 = B[(size_t)gk*N + gn];
                    if (gn + 1 < N) x1 = B[(size_t)gk*N + gn + 1];
                }
                unsigned long long p;
                PACK2(p, x0, x1);
                Bs2[k][n2] = p;
            }
        }
        __syncthreads();
#pragma unroll
        for (int kk = 0; kk < 16; kk++) {
            unsigned long long bb0 = Bs2[kk][txn*4 + 0];
            unsigned long long bb1 = Bs2[kk][txn*4 + 1];
            unsigned long long bb2 = Bs2[kk][txn*4 + 2];
            unsigned long long bb3 = Bs2[kk][txn*4 + 3];
#pragma unroll
            for (int i = 0; i < 8; i++) {
                unsigned long long aa = As2[kk][tym*8 + i];
                FMA2(acc2[i][0], aa, bb0);
                FMA2(acc2[i][1], aa, bb1);
                FMA2(acc2[i][2], aa, bb2);
                FMA2(acc2[i][3], aa, bb3);
            }
        }
        __syncthreads();
    }
#pragma unroll
    for (int i = 0; i < 8; i++) {
        int gm = m0 + tym*8 + i;
        if (gm >= M) continue;
#pragma unroll
        for (int j = 0; j < 4; j++) {
            float v0, v1;
            UNPACK2(v0, v1, acc2[i][j]);
            int gn0 = n0 + txn*8 + 2*j;
            if (gn0 < N) {
                float v = v0;
                if (bias) v += bias[gn0];
                if (reluOut) v = fmaxf(v, 0.f);
                C[(size_t)gm*N + gn0] = v;
            }
            if (gn0 + 1 < N) {
                float v = v1;
                if (bias) v += bias[gn0 + 1];
                if (reluOut) v = fmaxf(v, 0.f);
                C[(size_t)gm*N + gn0 + 1] = v;
            }
        }
    }
}

// ---------------- tiled fp32 GEMM (64x64, small-M), FFMA2 ----------------
__global__ __launch_bounds__(128)
void gemm_kernel(const float* __restrict__ A, const float* __restrict__ B,
                 float* __restrict__ C, int M, int N, int K,
                 const float* __restrict__ bias, int reluOut, int reluA, int addC)
{
    __shared__ float As[64][17];
    __shared__ float Bs[16][64];
    int m0 = blockIdx.y * 64;
    int n0 = blockIdx.x * 64;
    int tid = threadIdx.x;
    int ty = tid >> 4;
    int tx = tid & 15;
    unsigned long long acc2[8][2];
#pragma unroll
    for (int i = 0; i < 8; i++) {
        acc2[i][0] = 0ULL; acc2[i][1] = 0ULL;
    }

    for (int k0 = 0; k0 < K; k0 += 16) {
#pragma unroll
        for (int r = 0; r < 8; r++) {
            int t = tid + r*128;
            int m = t >> 4, k = t & 15;
            int gm = m0 + m, gk = k0 + k;
            float v = (gm < M && gk < K) ? A[(size_t)gm*K + gk] : 0.f;
            if (reluA) v = fmaxf(v, 0.f);
            As[m][k] = v;
        }
#pragma unroll
        for (int r = 0; r < 8; r++) {
            int t = tid + r*128;
            int k = t >> 6;
            int n = t & 63;
            int gk = k0 + k, gn = n0 + n;
            Bs[k][n] = (gk < K && gn < N) ? B[(size_t)gk*N + gn] : 0.f;
        }
        __syncthreads();
#pragma unroll
        for (int kk = 0; kk < 16; kk++) {
            float4 bq = *(const float4*)&Bs[kk][tx*4];
            unsigned long long bb0, bb1;
            PACK2(bb0, bq.x, bq.y);
            PACK2(bb1, bq.z, bq.w);
#pragma unroll
            for (int i = 0; i < 8; i++) {
                float av = As[ty*8 + i][kk];
                unsigned long long aa;
                PACK2(aa, av, av);
                FMA2(acc2[i][0], aa, bb0);
                FMA2(acc2[i][1], aa, bb1);
            }
        }
        __syncthreads();
    }
#pragma unroll
    for (int i = 0; i < 8; i++) {
        int gm = m0 + ty*8 + i;
        if (gm >= M) continue;
        float v[4];
        UNPACK2(v[0], v[1], acc2[i][0]);
        UNPACK2(v[2], v[3], acc2[i][1]);
#pragma unroll
        for (int j = 0; j < 4; j++) {
            int gn = n0 + tx*4 + j;
            if (gn >= N) continue;
            float val = v[j];
            if (bias) val += bias[gn];
            if (addC) val += C[(size_t)gm*N + gn];
            if (reluOut) val = fmaxf(val, 0.f);
            C[(size_t)gm*N + gn] = val;
        }
    }
}

// ---------------- fp32 split-K GEMM with implicit 3x3 im2col, FFMA2 ----------------
template<int C, int RELU>
__global__ __launch_bounds__(128)
void gemm_splitk_i3_kernel(const float* __restrict__ in, const float* __restrict__ B,
                           float* __restrict__ Cpart, int N, int Kc)
{
    __shared__ float As[64][17];
    __shared__ float Bs[16][64];
    const int M = POS2;
    const int K = 9*C;
    const int SH = (C == 128) ? 7 : 6;
    int m0 = blockIdx.y * 64;
    int n0 = blockIdx.x * 64;
    int s  = blockIdx.z;
    int kbeg = s * Kc;
    int kend = kbeg + Kc; if (kend > K) kend = K;
    int tid = threadIdx.x;
    int ty = tid >> 4;
    int tx = tid & 15;
    unsigned long long acc2[8][2];
#pragma unroll
    for (int i = 0; i < 8; i++) {
        acc2[i][0] = 0ULL; acc2[i][1] = 0ULL;
    }

    for (int k0 = kbeg; k0 < kend; k0 += 16) {
#pragma unroll
        for (int r = 0; r < 8; r++) {
            int t = tid + r*128;
            int m = t >> 4, k = t & 15;
            int gm = m0 + m, gk = k0 + k;
            float v = 0.f;
            if (gm < M && gk < kend) {
                int ic = gk & (C - 1);
                int rr = gk >> SH;
                int kw = rr % 3, kh = rr / 3;
                int ow = gm % W2;
                int r2 = gm / W2;
                int oh = r2 % H2;
                int b  = r2 / H2;
                int ihh = oh + kh - 1, iww = ow + kw - 1;
                if (ihh >= 0 && ihh < H2 && iww >= 0 && iww < W2) {
                    v = in[((size_t)((b*H2 + ihh)*W2 + iww))*C + ic];
                    if (RELU) v = fmaxf(v, 0.f);
                }
            }
            As[m][k] = v;
        }
#pragma unroll
        for (int r = 0; r < 8; r++) {
            int t = tid + r*128;
            int k = t >> 6;
            int n = t & 63;
            int gk = k0 + k, gn = n0 + n;
            Bs[k][n] = (gk < kend && gn < N) ? B[(size_t)gk*N + gn] : 0.f;
        }
        __syncthreads();
#pragma unroll
        for (int kk = 0; kk < 16; kk++) {
            float4 bq = *(const float4*)&Bs[kk][tx*4];
            unsigned long long bb0, bb1;
            PACK2(bb0, bq.x, bq.y);
            PACK2(bb1, bq.z, bq.w);
#pragma unroll
            for (int i = 0; i < 8; i++) {
                float av = As[ty*8 + i][kk];
                unsigned long long aa;
                PACK2(aa, av, av);
                FMA2(acc2[i][0], aa, bb0);
                FMA2(acc2[i][1], aa, bb1);
            }
        }
        __syncthreads();
    }
    float* Cs = Cpart + (size_t)s * M * N;
#pragma unroll
    for (int i = 0; i < 8; i++) {
        int gm = m0 + ty*8 + i;
        if (gm >= M) continue;
        float v[4];
        UNPACK2(v[0], v[1], acc2[i][0]);
        UNPACK2(v[2], v[3], acc2[i][1]);
#pragma unroll
        for (int j = 0; j < 4; j++) {
            int gn = n0 + tx*4 + j;
            if (gn >= N) continue;
            Cs[(size_t)gm*N + gn] = v[j];
        }
    }
}

__global__ void reduce_splitk_kernel(const float* __restrict__ Cpart, float* __restrict__ C,
                                     int MN, int N, int S, const float* __restrict__ bias,
                                     int reluOut, int addC)
{
    int t = blockIdx.x * blockDim.x + threadIdx.x;
    if (t >= MN) return;
    float v = 0.f;
    for (int s = 0; s < S; s++) v += Cpart[(size_t)s*MN + t];
    if (bias) v += bias[t % N];
    if (addC) v += C[t];
    if (reluOut) v = fmaxf(v, 0.f);
    C[t] = v;
}

// ---------------- VQ ----------------
__global__ void vq_setup_kernel(const float* __restrict__ emb, float* __restrict__ esq,
                                int* __restrict__ counts, float* __restrict__ sqacc) {
    int k = threadIdx.x;
    float s = 0.f;
    const float* e = emb + k*64;
#pragma unroll
    for (int d = 0; d < 64; d++) s = fmaf(e[d], e[d], s);
    esq[k] = s;
    counts[k] = 0;
    if (k == 0) sqacc[0] = 0.f;
}

__global__ void vq_kernel(const float* __restrict__ z, const float* __restrict__ emb,
                          const float* __restrict__ esq, int* __restrict__ idx,
                          float* __restrict__ q, int* __restrict__ counts,
                          float* __restrict__ sqacc)
{
    __shared__ float zs[64];
    __shared__ float sb[128];
    __shared__ int   si[128];
    int pos = blockIdx.x;
    int tid = threadIdx.x;
    if (tid < 64) zs[tid] = z[pos*64 + tid];
    __syncthreads();
    float best = 3.4e38f; int bi = 0x7fffffff;
    for (int k = tid; k < KE; k += 128) {
        const float* e = emb + k*64;
        float dot = 0.f;
#pragma unroll
        for (int d = 0; d < 64; d++) dot = fmaf(e[d], zs[d], dot);
        float s = esq[k] - 2.f*dot;
        if (s < best || (s == best && k < bi)) { best = s; bi = k; }
    }
    sb[tid] = best; si[tid] = bi;
    __syncthreads();
    for (int off = 64; off > 0; off >>= 1) {
        if (tid < off) {
            float s2 = sb[tid+off]; int i2 = si[tid+off];
            if (s2 < sb[tid] || (s2 == sb[tid] && i2 < si[tid])) { sb[tid] = s2; si[tid] = i2; }
        }
        __syncthreads();
    }
    int bk = si[0];
    if (tid == 0) { idx[pos] = bk; atomicAdd(&counts[bk], 1); }
    __syncthreads();
    float v = 0.f;
    if (tid < 64) {
        float qv = emb[bk*64 + tid];
        q[pos*64 + tid] = qv;
        float d = qv - zs[tid];
        v = d*d;
    }
    sb[tid] = v;
    __syncthreads();
    for (int off = 64; off > 0; off >>= 1) {
        if (tid < off) sb[tid] += sb[tid+off];
        __syncthreads();
    }
    if (tid == 0) atomicAdd(sqacc, sb[0]);
}

__global__ void finalize_kernel(const int* __restrict__ counts, const float* __restrict__ sqacc,
                                float* __restrict__ out, long outN) {
    __shared__ float sh[512];
    int tid = threadIdx.x;
    float p = (float)counts[tid] / 960.f;
    sh[tid] = p * logf(p + 1e-10f);
    __syncthreads();
    for (int off = 256; off > 0; off >>= 1) {
        if (tid < off) sh[tid] += sh[tid+off];
        __syncthreads();
    }
    if (tid == 0) {
        out[0] = 1.25f * sqacc[0] / (float)(POS2*64);
        out[outN-1] = expf(-sh[0]);
    }
}

// ---------------- convT gathers ----------------
__global__ void gather_t1_kernel(const float* __restrict__ Y1, const float* __restrict__ bias,
                                 float* __restrict__ t1) {
    int t = blockIdx.x * blockDim.x + threadIdx.x;
    if (t >= POSD*16) return;
    int oc = (t & 15) * 4;
    int pos = t >> 4;
    int ow = pos % TW; int r = pos / TW;
    int oh = r % TH; int b = r / TH;
    float4 acc = *(const float4*)(bias + oc);
    int lo = oh - 10;
    int ih_lo = lo <= 0 ? 0 : (lo + 9)/10;
    int ih_hi = (oh + 1)/10; if (ih_hi > 4) ih_hi = 4;
    int lw = ow - 10;
    int iw_lo = lw <= 0 ? 0 : (lw + 9)/10;
    int iw_hi = (ow + 1)/10; if (iw_hi > 5) iw_hi = 5;
    for (int ih = ih_lo; ih <= ih_hi; ih++) {
        int kh = oh + 1 - 10*ih;
        for (int iw = iw_lo; iw <= iw_hi; iw++) {
            int kw = ow + 1 - 10*iw;
            float4 y = *(const float4*)(Y1 + (size_t)((b*5 + ih)*6 + iw)*NT1 + (kh*12 + kw)*64 + oc);
            acc.x += y.x; acc.y += y.y; acc.z += y.z; acc.w += y.w;
        }
    }
    acc.x = fmaxf(acc.x, 0.f); acc.y = fmaxf(acc.y, 0.f);
    acc.z = fmaxf(acc.z, 0.f); acc.w = fmaxf(acc.w, 0.f);
    *(float4*)(t1 + (size_t)pos*64 + oc) = acc;
}

// gather_recon v2: block per (b, oh); stage contributing Y2 rows in smem.
__global__ __launch_bounds__(128)
void gather_recon2_kernel(const float* __restrict__ Y2, const float* __restrict__ bias,
                          float* __restrict__ out)
{
    __shared__ float s[2][1320];
    int blk = blockIdx.x;
    int oh = blk % OHH;
    int b  = blk / OHH;
    int lo = oh - 8;
    int ih_lo = lo <= 0 ? 0 : (lo + 7)/8;
    int ih_hi = (oh + 1)/8; if (ih_hi > TH-1) ih_hi = TH-1;
    int nih = ih_hi - ih_lo + 1;
    int tid = threadIdx.x;
    for (int i = 0; i < nih; i++) {
        int ih = ih_lo + i;
        int kh = oh + 1 - 8*ih;
        const float* src = Y2 + (size_t)((b*TH + ih)*TW)*NT2 + kh*22;
        for (int t = tid; t < 1320; t += 128) {
            int c = t / 22, o = t % 22;
            s[i][t] = src[(size_t)c*NT2 + o];
        }
    }
    __syncthreads();
    float b0 = bias[0], b1 = bias[1];
    for (int t = tid; t < 2*OWW; t += 128) {
        int ow = t % OWW;
        int oc = t / OWW;
        int lw = ow - 9;
        int iw_lo = lw <= 0 ? 0 : (lw + 8)/9;
        int iw_hi = (ow + 1)/9; if (iw_hi > TW-1) iw_hi = TW-1;
        float acc = oc ? b1 : b0;
        for (int i = 0; i < nih; i++)
            for (int iw = iw_lo; iw <= iw_hi; iw++) {
                int kw = ow + 1 - 9*iw;
                acc += s[i][iw*22 + kw*2 + oc];
            }
        out[(((size_t)(b*2 + oc))*OHH + oh)*OWW + ow] = acc;
    }
}

// ---------------- host ----------------
static inline void launch_gemm128(const float* A, const float* B, float* C,
                                  int M, int N, int K, const float* bias,
                                  int reluOut, int reluA) {
    dim3 grid((N + 63)/64, (M + 127)/128);
    gemm128_kernel<<<grid, 128>>>(A, B, C, M, N, K, bias, reluOut, reluA);
}

static inline void launch_gemm_tf32(const float* A, const float* B, float* C,
                                    int M, int N, int K, int reluA) {
    dim3 grid((N + 63)/64, (M + 127)/128);
    gemm_tf32_kernel<<<grid, 256>>>(A, B, C, M, N, K, reluA);
}

static inline void launch_gemm(const float* A, const float* B, float* C,
                               int M, int N, int K, const float* bias,
                               int reluOut, int reluA, int addC) {
    dim3 grid((N + 63)/64, (M + 63)/64);
    gemm_kernel<<<grid, 128>>>(A, B, C, M, N, K, bias, reluOut, reluA, addC);
}

template<int C, int RELU>
static inline void launch_i3_splitk(const float* in, const float* B, float* Cout, float* part,
                                    int N, int S, const float* bias, int reluOut, int addC) {
    int K = 9*C;
    int Kc = (K + S - 1) / S;
    Kc = ((Kc + 15) / 16) * 16;
    S  = (K + Kc - 1) / Kc;
    dim3 grid((N + 63)/64, (POS2 + 63)/64, S);
    gemm_splitk_i3_kernel<C, RELU><<<grid, 128>>>(in, B, part, N, Kc);
    int MN = POS2 * N;
    reduce_splitk_kernel<<<(MN + 255)/256, 256>>>(part, Cout, MN, N, S, bias, reluOut, addC);
}

extern "C" void kernel_launch(void* const* d_in, const int* in_sizes, int n_in,
                              void* d_out, int out_size) {
    const float* x       = (const float*)d_in[0];
    const float* enc_w1  = (const float*)d_in[1];
    const float* enc_b1  = (const float*)d_in[2];
    const float* enc_w2  = (const float*)d_in[3];
    const float* enc_b2  = (const float*)d_in[4];
    const float* enc_w3  = (const float*)d_in[5];
    const float* enc_b3  = (const float*)d_in[6];
    const float* enc_rw1 = (const float*)d_in[7];
    const float* enc_rw2 = (const float*)d_in[8];
    const float* pre_w   = (const float*)d_in[9];
    const float* pre_b   = (const float*)d_in[10];
    const float* emb     = (const float*)d_in[11];
    const float* dec_w1  = (const float*)d_in[12];
    const float* dec_b1  = (const float*)d_in[13];
    const float* dec_rw1 = (const float*)d_in[14];
    const float* dec_rw2 = (const float*)d_in[15];
    const float* dec_tw1 = (const float*)d_in[16];
    const float* dec_tb1 = (const float*)d_in[17];
    const float* dec_tw2 = (const float*)d_in[18];
    const float* dec_tb2 = (const float*)d_in[19];
    float* out = (float*)d_out;

    float *p_A1, *p_h1, *p_col, *p_hA, *p_hB, *p_t64, *p_z, *p_q, *p_part;
    float *p_Y1, *p_t1, *p_Y2;
    float *p_w1t, *p_w2t, *p_w3t, *p_er1t, *p_er2t, *p_pret, *p_d1t, *p_dr1t, *p_dr2t;
    float *p_tw1t, *p_tw2t, *p_esq, *p_sqacc;
    int *p_counts, *p_idx;
    cudaGetSymbolAddress((void**)&p_A1, g_A1);
    cudaGetSymbolAddress((void**)&p_h1, g_h1);
    cudaGetSymbolAddress((void**)&p_col, g_col);
    cudaGetSymbolAddress((void**)&p_hA, g_hA);
    cudaGetSymbolAddress((void**)&p_hB, g_hB);
    cudaGetSymbolAddress((void**)&p_t64, g_t64);
    cudaGetSymbolAddress((void**)&p_z, g_z);
    cudaGetSymbolAddress((void**)&p_q, g_q);
    cudaGetSymbolAddress((void**)&p_part, g_part);
    cudaGetSymbolAddress((void**)&p_Y1, g_Y1);
    cudaGetSymbolAddress((void**)&p_t1, g_t1);
    cudaGetSymbolAddress((void**)&p_Y2, g_Y2);
    cudaGetSymbolAddress((void**)&p_w1t, g_w1t);
    cudaGetSymbolAddress((void**)&p_w2t, g_w2t);
    cudaGetSymbolAddress((void**)&p_w3t, g_w3t);
    cudaGetSymbolAddress((void**)&p_er1t, g_er1t);
    cudaGetSymbolAddress((void**)&p_er2t, g_er2t);
    cudaGetSymbolAddress((void**)&p_pret, g_pret);
    cudaGetSymbolAddress((void**)&p_d1t, g_d1t);
    cudaGetSymbolAddress((void**)&p_dr1t, g_dr1t);
    cudaGetSymbolAddress((void**)&p_dr2t, g_dr2t);
    cudaGetSymbolAddress((void**)&p_tw1t, g_tw1t);
    cudaGetSymbolAddress((void**)&p_tw2t, g_tw2t);
    cudaGetSymbolAddress((void**)&p_esq, g_esq);
    cudaGetSymbolAddress((void**)&p_sqacc, g_sqacc);
    cudaGetSymbolAddress((void**)&p_counts, g_counts);
    cudaGetSymbolAddress((void**)&p_idx, g_idx);

    // ---- ONE merged weight-transpose kernel ----
    {
        TJobs J;
        int j = 0;
        long off = 0;
        auto add = [&](const float* s, float* d, int co, int ci, int kh, int kw, int isT) {
            J.src[j] = s; J.dst[j] = d;
            J.cout[j] = co; J.cin[j] = ci; J.kh[j] = kh; J.kw[j] = kw; J.isT[j] = isT;
            J.off[j] = off;
            off += (long)co*ci*kh*kw;
            j++;
        };
        add(enc_w1,            p_w1t,            64, 2,  10, 11, 0);
        add(enc_w2,            p_w2t,            128,64, 12, 12, 0);
        add(enc_w3,            p_w3t,            128,128, 3,  3, 0);
        add(enc_rw1,           p_er1t,            64,128, 3,  3, 0);
        add(enc_rw1 + 73728,   p_er1t + 73728,    64,128, 3,  3, 0);
        add(enc_rw2,           p_er2t,           128, 64, 1,  1, 0);
        add(enc_rw2 + 8192,    p_er2t + 8192,    128, 64, 1,  1, 0);
        add(pre_w,             p_pret,            64,128, 1,  1, 0);
        add(dec_w1,            p_d1t,            128, 64, 3,  3, 0);
        add(dec_rw1,           p_dr1t,            64,128, 3,  3, 0);
        add(dec_rw1 + 73728,   p_dr1t + 73728,    64,128, 3,  3, 0);
        add(dec_rw2,           p_dr2t,           128, 64, 1,  1, 0);
        add(dec_rw2 + 8192,    p_dr2t + 8192,    128, 64, 1,  1, 0);
        add(dec_tw1,           p_tw1t,            64,128, 12, 12, 1);
        add(dec_tw2,           p_tw2t,             2, 64, 10, 11, 1);
        J.off[NJOBS] = off;
        long blocks = (off + 255)/256;
        wtrans_all_kernel<<<(unsigned)blocks, 256>>>(J);
    }

    // ---- encoder (fp32-accurate; safe for VQ argmin) ----
    {
        int total2 = POS1 * (K1/2);
        im2col_c1_kernel<<<(total2 + 255)/256, 256>>>(x, p_A1);
    }
    launch_gemm128(p_A1, p_w1t, p_h1, POS1, OC1, K1, enc_b1, 1, 0);

    // conv2: explicit im2col + 3xTF32 split-K (S=16)
    {
        int total4 = POS2 * 12*12*16;
        im2col4_c2_kernel<<<(total4 + 255)/256, 256>>>(p_h1, p_col);
        int S = 16;
        int Kc = K2 / S;
        dim3 grid(2, (POS2 + 127)/128, S);
        gemm3x_kernel<<<grid, 256>>>(p_col, p_w2t, p_part, POS2, 128, K2, Kc);
        int MN = POS2 * 128;
        reduce_splitk_kernel<<<(MN + 255)/256, 256>>>(p_part, p_hA, MN, 128, S, enc_b2, 1, 0);
    }

    // conv3 (implicit 3x3)
    launch_i3_splitk<128, 0>(p_hA, p_w3t, p_hB, p_part, 128, 8, enc_b3, 0, 0);

    for (int i = 0; i < 2; i++) {    // enc res stack
        launch_i3_splitk<128, 1>(p_hB, p_er1t + i*1152*64, p_t64, p_part, 64, 8, 0, 1, 0);
        launch_gemm(p_t64, p_er2t + i*64*128, p_hB, POS2, 128, 64, 0, 0, 0, 1);
    }
    launch_gemm(p_hB, p_pret, p_z, POS2, 64, 128, pre_b, 0, 1, 0);

    // ---- VQ ----
    vq_setup_kernel<<<1, KE>>>(emb, p_esq, p_counts, p_sqacc);
    vq_kernel<<<POS2, 128>>>(p_z, emb, p_esq, p_idx, p_q, p_counts, p_sqacc);
    finalize_kernel<<<1, KE>>>(p_counts, p_sqacc, out, (long)out_size);

    // ---- decoder ----
    launch_i3_splitk<64, 0>(p_q, p_d1t, p_hA, p_part, 128, 4, dec_b1, 0, 0);

    for (int i = 0; i < 2; i++) {    // dec res stack
        launch_i3_splitk<128, 1>(p_hA, p_dr1t + i*1152*64, p_t64, p_part, 64, 8, 0, 1, 0);
        launch_gemm(p_t64, p_dr2t + i*64*128, p_hA, POS2, 128, 64, 0, 0, 0, 1);
    }

    // convT1: tf32 GEMM (relu on input) + gather (+bias, relu)
    launch_gemm_tf32(p_hA, p_tw1t, p_Y1, POS2, NT1, 128, 1);
    gather_t1_kernel<<<(POSD*16 + 255)/256, 256>>>(p_Y1, dec_tb1, p_t1);

    // convT2: tf32 GEMM + smem-staged gather (+bias) -> recon at out+1
    launch_gemm_tf32(p_t1, p_tw2t, p_Y2, POSD, NT2, 64, 0);
    gather_recon2_kernel<<<NB*OHH, 128>>>(p_Y2, dec_tb2, out + 1);
}

// round 17
// speedup vs baseline: 1.0607x; 1.0607x over previous
#include <cuda_runtime.h>
#include <math.h>
#include <stdint.h>

// ---------------- dimensions ----------------
#define NB   32
#define C0   2
#define H0   400
#define W0   600
#define KH1  10
#define KW1  11
#define H1   50
#define W1   66
#define OC1  64
#define POS1 (NB*H1*W1)          // 105600
#define K1   (KH1*KW1*C0)        // 220
#define H2   5
#define W2   6
#define POS2 (NB*H2*W2)          // 960
#define K2   (12*12*64)          // 9216
#define KE   512
#define TH   50
#define TW   60
#define POSD (NB*TH*TW)          // 96000
#define NT1  (12*12*64)          // 9216
#define NT2  (10*11*2)           // 220
#define OHH  400
#define OWW  540
#define RECON_N (NB*2*OHH*OWW)   // 13824000

// ---------------- f32x2 packed FMA (sm_103a) ----------------
#define PACK2(d, lo, hi) asm("mov.b64 %0, {%1, %2};" : "=l"(d) : "f"(lo), "f"(hi))
#define UNPACK2(lo, hi, d) asm("mov.b64 {%0, %1}, %2;" : "=f"(lo), "=f"(hi) : "l"(d))
#define FMA2(d, a, b) asm("fma.rn.f32x2 %0, %1, %2, %0;" : "+l"(d) : "l"(a), "l"(b))

// ---------------- scratch ----------------
__device__ float g_A1  [(size_t)POS1*K1];
__device__ float g_h1  [(size_t)POS1*OC1];
__device__ float g_col [(size_t)POS2*K2];
__device__ float g_hA  [POS2*128];
__device__ float g_hB  [POS2*128];
__device__ float g_t64 [POS2*64];
__device__ float g_z   [POS2*64];
__device__ float g_q   [POS2*64];
__device__ float g_part[16*POS2*128];
__device__ float g_Y1  [(size_t)POS2*NT1];
__device__ float g_t1  [(size_t)POSD*64];
__device__ float g_Y2  [(size_t)POSD*NT2];
__device__ float g_w1t [K1*OC1];
__device__ float g_w2t [K2*128];
__device__ float g_w3t [9*128*128];
__device__ float g_er1t[2*9*128*64];
__device__ float g_er2t[2*64*128];
__device__ float g_pret[128*64];
__device__ float g_d1t [9*64*128];
__device__ float g_dr1t[2*9*128*64];
__device__ float g_dr2t[2*64*128];
__device__ float g_tw1t[128*NT1];
__device__ float g_tw2t[64*NT2];
__device__ float g_esq [KE];
__device__ int   g_counts[KE];
__device__ float g_sqacc[1];
__device__ int   g_idx [POS2];

// ---------------- merged weight transpose ----------------
#define NJOBS 15
struct TJobs {
    const float* src[NJOBS];
    float*       dst[NJOBS];
    int cout[NJOBS], cin[NJOBS], kh[NJOBS], kw[NJOBS], isT[NJOBS];
    long off[NJOBS+1];
};

__global__ void wtrans_all_kernel(TJobs J) {
    long t = (long)blockIdx.x * blockDim.x + threadIdx.x;
    if (t >= J.off[NJOBS]) return;
    int j = 0;
#pragma unroll
    for (int i = 0; i < NJOBS-1; i++) j += (t >= J.off[i+1]) ? 1 : 0;
    long u = t - J.off[j];
    int Cout = J.cout[j], Cin = J.cin[j], KH = J.kh[j], KW = J.kw[j];
    int oc = (int)(u % Cout); long r = u / Cout;
    if (!J.isT[j]) {
        int ic = (int)(r % Cin);
        int kk = (int)(r / Cin);
        int khh = kk / KW, kww = kk % KW;
        J.dst[j][u] = J.src[j][((oc*Cin + ic)*KH + khh)*KW + kww];
    } else {
        int khw = KH*KW;
        int kk = (int)(r % khw);
        int ic = (int)(r / khw);
        J.dst[j][u] = J.src[j][(ic*Cout + oc)*khw + kk];
    }
}

// ---------------- conv1 im2col: NCHW in, C0=2, float2 store ----------------
__global__ void im2col_c1_kernel(const float* __restrict__ in, float* __restrict__ out) {
    const int total2 = POS1 * (K1/2);
    int t = blockIdx.x * blockDim.x + threadIdx.x;
    if (t >= total2) return;
    int k2  = t % 110;
    int pos = t / 110;
    int kw = k2 % 11;
    int kh = k2 / 11;
    int ow = pos % W1;
    int r2 = pos / W1;
    int oh = r2 % H1;
    int b  = r2 / H1;
    int ih = oh*8 - 1 + kh;
    int iw = ow*9 - 1 + kw;
    float v0 = 0.f, v1 = 0.f;
    if (ih >= 0 && ih < H0 && iw >= 0 && iw < W0) {
        long base = (((long)b*2)*H0 + ih)*W0 + iw;
        v0 = in[base];
        v1 = in[base + (long)H0*W0];
    }
    *(float2*)(out + (size_t)t*2) = make_float2(v0, v1);
}

// ---------------- conv2 explicit im2col (4 ch/thread, float4) ----------------
__global__ void im2col4_c2_kernel(const float* __restrict__ in, float* __restrict__ out) {
    const int total4 = POS2 * 12*12*16;
    int t = blockIdx.x * blockDim.x + threadIdx.x;
    if (t >= total4) return;
    const int KC4 = 12*12*16;
    int k4  = t % KC4;
    int pos = t / KC4;
    int ic = (k4 & 15) * 4;
    int r  = k4 >> 4;
    int kw = r % 12;
    int kh = r / 12;
    int ow = pos % W2;
    int r2 = pos / W2;
    int oh = r2 % H2;
    int b  = r2 / H2;
    int ih = oh*10 - 1 + kh;
    int iw = ow*10 - 1 + kw;
    float4 v = make_float4(0.f, 0.f, 0.f, 0.f);
    if (ih >= 0 && ih < H1 && iw >= 0 && iw < W1)
        v = *(const float4*)(in + (((long)(b*H1 + ih))*W1 + iw)*64 + ic);
    *(float4*)(out + (size_t)t*4) = v;
}

// ---------------- tf32 helpers ----------------
__device__ __forceinline__ uint32_t f2tf32(float x) {
    uint32_t r;
    asm("cvt.rna.tf32.f32 %0, %1;" : "=r"(r) : "f"(x));
    return r;
}
__device__ __forceinline__ void split3(float v, uint32_t& hi, uint32_t& lo) {
    hi = f2tf32(v);
    lo = f2tf32(v - __uint_as_float(hi));
}
#define MMA_TF32(acc, a0,a1,a2,a3, b0,b1) \
    asm volatile( \
        "mma.sync.aligned.m16n8k8.row.col.f32.tf32.tf32.f32 " \
        "{%0,%1,%2,%3}, {%4,%5,%6,%7}, {%8,%9}, {%0,%1,%2,%3};" \
        : "+f"((acc)[0]), "+f"((acc)[1]), "+f"((acc)[2]), "+f"((acc)[3]) \
        : "r"(a0), "r"(a1), "r"(a2), "r"(a3), "r"(b0), "r"(b1))

// ---------------- 3xTF32 GEMM (fp32-accurate, tensor cores; split-K, explicit A) ----------------
__global__ __launch_bounds__(256)
void gemm3x_kernel(const float* __restrict__ A, const float* __restrict__ B,
                   float* __restrict__ Cpart, int M, int N, int K, int Kc)
{
    __shared__ float As[128][17];
    __shared__ float Bs[16][72];
    int m0 = blockIdx.y * 128;
    int n0 = blockIdx.x * 64;
    int s  = blockIdx.z;
    int kbeg = s * Kc;
    int kend = kbeg + Kc; if (kend > K) kend = K;
    int tid = threadIdx.x;
    int warp = tid >> 5, lane = tid & 31;
    int wm = warp >> 1, wn = warp & 1;
    int g = lane >> 2, tg = lane & 3;

    float acc[2][4][4];
#pragma unroll
    for (int mi = 0; mi < 2; mi++)
#pragma unroll
        for (int ni = 0; ni < 4; ni++)
#pragma unroll
            for (int c = 0; c < 4; c++) acc[mi][ni][c] = 0.f;

    for (int k0 = kbeg; k0 < kend; k0 += 16) {
#pragma unroll
        for (int r = 0; r < 8; r++) {
            int t = tid + r*256;
            int m = t >> 4, k = t & 15;
            int gm = m0 + m, gk = k0 + k;
            As[m][k] = (gm < M && gk < kend) ? A[(size_t)gm*K + gk] : 0.f;
        }
#pragma unroll
        for (int r = 0; r < 4; r++) {
            int t = tid + r*256;
            int k = t >> 6, n = t & 63;
            int gk = k0 + k, gn = n0 + n;
            Bs[k][n] = (gk < kend && gn < N) ? B[(size_t)gk*N + gn] : 0.f;
        }
        __syncthreads();
#pragma unroll
        for (int kk = 0; kk < 16; kk += 8) {
            uint32_t ah[2][4], al[2][4], bh[4][2], bl[4][2];
#pragma unroll
            for (int mi = 0; mi < 2; mi++) {
                int mrow = wm*32 + mi*16;
                split3(As[mrow + g    ][kk + tg    ], ah[mi][0], al[mi][0]);
                split3(As[mrow + g + 8][kk + tg    ], ah[mi][1], al[mi][1]);
                split3(As[mrow + g    ][kk + tg + 4], ah[mi][2], al[mi][2]);
                split3(As[mrow + g + 8][kk + tg + 4], ah[mi][3], al[mi][3]);
            }
#pragma unroll
            for (int ni = 0; ni < 4; ni++) {
                int ncol = wn*32 + ni*8 + g;
                split3(Bs[kk + tg    ][ncol], bh[ni][0], bl[ni][0]);
                split3(Bs[kk + tg + 4][ncol], bh[ni][1], bl[ni][1]);
            }
#pragma unroll
            for (int mi = 0; mi < 2; mi++)
#pragma unroll
                for (int ni = 0; ni < 4; ni++) {
                    MMA_TF32(acc[mi][ni], ah[mi][0],ah[mi][1],ah[mi][2],ah[mi][3], bl[ni][0],bl[ni][1]);
                    MMA_TF32(acc[mi][ni], al[mi][0],al[mi][1],al[mi][2],al[mi][3], bh[ni][0],bh[ni][1]);
                    MMA_TF32(acc[mi][ni], ah[mi][0],ah[mi][1],ah[mi][2],ah[mi][3], bh[ni][0],bh[ni][1]);
                }
        }
        __syncthreads();
    }
    float* Cs = Cpart + (size_t)s*M*N;
#pragma unroll
    for (int mi = 0; mi < 2; mi++) {
#pragma unroll
        for (int ni = 0; ni < 4; ni++) {
            int gmA = m0 + wm*32 + mi*16 + g;
            int gmB = gmA + 8;
            int gn0 = n0 + wn*32 + ni*8 + 2*tg;
            if (gmA < M) {
                if (gn0     < N) Cs[(size_t)gmA*N + gn0    ] = acc[mi][ni][0];
                if (gn0 + 1 < N) Cs[(size_t)gmA*N + gn0 + 1] = acc[mi][ni][1];
            }
            if (gmB < M) {
                if (gn0     < N) Cs[(size_t)gmB*N + gn0    ] = acc[mi][ni][2];
                if (gn0 + 1 < N) Cs[(size_t)gmB*N + gn0 + 1] = acc[mi][ni][3];
            }
        }
    }
}

// ---------------- plain tf32 GEMM (decoder only) ----------------
__global__ __launch_bounds__(256)
void gemm_tf32_kernel(const float* __restrict__ A, const float* __restrict__ B,
                      float* __restrict__ C, int M, int N, int K, int reluA)
{
    __shared__ uint32_t As[128][17];
    __shared__ uint32_t Bs[16][72];
    int m0 = blockIdx.y * 128;
    int n0 = blockIdx.x * 64;
    int tid = threadIdx.x;
    int warp = tid >> 5, lane = tid & 31;
    int wm = warp >> 1, wn = warp & 1;
    int groupID = lane >> 2, tig = lane & 3;

    float acc[2][4][4];
#pragma unroll
    for (int mi = 0; mi < 2; mi++)
#pragma unroll
        for (int ni = 0; ni < 4; ni++)
#pragma unroll
            for (int c = 0; c < 4; c++) acc[mi][ni][c] = 0.f;

    for (int k0 = 0; k0 < K; k0 += 16) {
#pragma unroll
        for (int r = 0; r < 8; r++) {
            int t = tid + r*256;
            int m = t >> 4, k = t & 15;
            int gm = m0 + m, gk = k0 + k;
            float v = (gm < M && gk < K) ? A[(size_t)gm*K + gk] : 0.f;
            if (reluA) v = fmaxf(v, 0.f);
            As[m][k] = f2tf32(v);
        }
#pragma unroll
        for (int r = 0; r < 4; r++) {
            int t = tid + r*256;
            int k = t >> 6, n = t & 63;
            int gk = k0 + k, gn = n0 + n;
            float v = (gk < K && gn < N) ? B[(size_t)gk*N + gn] : 0.f;
            Bs[k][n] = f2tf32(v);
        }
        __syncthreads();
#pragma unroll
        for (int kk = 0; kk < 16; kk += 8) {
            uint32_t a[2][4], b[4][2];
#pragma unroll
            for (int mi = 0; mi < 2; mi++) {
                int mrow = wm*32 + mi*16;
                a[mi][0] = As[mrow + groupID    ][kk + tig    ];
                a[mi][1] = As[mrow + groupID + 8][kk + tig    ];
                a[mi][2] = As[mrow + groupID    ][kk + tig + 4];
                a[mi][3] = As[mrow + groupID + 8][kk + tig + 4];
            }
#pragma unroll
            for (int ni = 0; ni < 4; ni++) {
                int ncol = wn*32 + ni*8 + groupID;
                b[ni][0] = Bs[kk + tig    ][ncol];
                b[ni][1] = Bs[kk + tig + 4][ncol];
            }
#pragma unroll
            for (int mi = 0; mi < 2; mi++)
#pragma unroll
                for (int ni = 0; ni < 4; ni++)
                    MMA_TF32(acc[mi][ni], a[mi][0],a[mi][1],a[mi][2],a[mi][3], b[ni][0],b[ni][1]);
        }
        __syncthreads();
    }
#pragma unroll
    for (int mi = 0; mi < 2; mi++) {
#pragma unroll
        for (int ni = 0; ni < 4; ni++) {
            int gmA = m0 + wm*32 + mi*16 + groupID;
            int gmB = gmA + 8;
            int gn0 = n0 + wn*32 + ni*8 + 2*tig;
            if (gmA < M) {
                if (gn0     < N) C[(size_t)gmA*N + gn0    ] = acc[mi][ni][0];
                if (gn0 + 1 < N) C[(size_t)gmA*N + gn0 + 1] = acc[mi][ni][1];
            }
            if (gmB < M) {
                if (gn0     < N) C[(size_t)gmB*N + gn0    ] = acc[mi][ni][2];
                if (gn0 + 1 < N) C[(size_t)gmB*N + gn0 + 1] = acc[mi][ni][3];
            }
        }
    }
}

// ---------------- gemm128 (conv1): 128x64 tile, 8x8 micro, FFMA2 ----------------
__global__ __launch_bounds__(128)
void gemm128_kernel(const float* __restrict__ A, const float* __restrict__ B,
                    float* __restrict__ C, int M, int N, int K,
                    const float* __restrict__ bias, int reluOut, int reluA)
{
    __shared__ float As[128][17];
    __shared__ float Bs[16][64];
    int m0 = blockIdx.y * 128;
    int n0 = blockIdx.x * 64;
    int tid = threadIdx.x;
    int tym = tid >> 3;
    int txn = tid & 7;
    unsigned long long acc2[8][4];
#pragma unroll
    for (int i = 0; i < 8; i++)
#pragma unroll
        for (int j = 0; j < 4; j++) acc2[i][j] = 0ULL;

    for (int k0 = 0; k0 < K; k0 += 16) {
#pragma unroll
        for (int r = 0; r < 16; r++) {
            int t = tid + r*128;
            int m = t >> 4, k = t & 15;
            int gm = m0 + m, gk = k0 + k;
            float v = (gm < M && gk < K) ? A[(size_t)gm*K + gk] : 0.f;
            if (reluA) v = fmaxf(v, 0.f);
            As[m][k] = v;
        }
        {
            int n = tid & 63;
            int kb = tid >> 6;
#pragma unroll
            for (int r = 0; r < 8; r++) {
                int k = kb + r*2;
                int gk = k0 + k, gn = n0 + n;
                Bs[k][n] = (gk < K && gn < N) ? B[(size_t)gk*N + gn] : 0.f;
            }
        }
        __syncthreads();
#pragma unroll
        for (int kk = 0; kk < 16; kk++) {
            float4 b0 = *(const float4*)&Bs[kk][txn*8];
            float4 b1 = *(const float4*)&Bs[kk][txn*8 + 4];
            unsigned long long bb[4];
            PACK2(bb[0], b0.x, b0.y);
            PACK2(bb[1], b0.z, b0.w);
            PACK2(bb[2], b1.x, b1.y);
            PACK2(bb[3], b1.z, b1.w);
#pragma unroll
            for (int i = 0; i < 8; i++) {
                float av = As[tym*8 + i][kk];
                unsigned long long aa;
                PACK2(aa, av, av);
#pragma unroll
                for (int j = 0; j < 4; j++)
                    FMA2(acc2[i][j], aa, bb[j]);
            }
        }
        __syncthreads();
    }
#pragma unroll
    for (int i = 0; i < 8; i++) {
        int gm = m0 + tym*8 + i;
        if (gm >= M) continue;
#pragma unroll
        for (int j = 0; j < 4; j++) {
            float v0, v1;
            UNPACK2(v0, v1, acc2[i][j]);
            int gn0 = n0 + txn*8 + 2*j;
            if (gn0 < N) {
                float v = v0;
                if (bias) v += bias[gn0];
                if (reluOut) v = fmaxf(v, 0.f);
                C[(size_t)gm*N + gn0] = v;
            }
            if (gn0 + 1 < N) {
                float v = v1;
                if (bias) v += bias[gn0 + 1];
                if (reluOut) v = fmaxf(v, 0.f);
                C[(size_t)gm*N + gn0 + 1] = v;
            }
        }
    }
}

// ---------------- tiled fp32 GEMM (64x64, small-M), FFMA2 ----------------
__global__ __launch_bounds__(128)
void gemm_kernel(const float* __restrict__ A, const float* __restrict__ B,
                 float* __restrict__ C, int M, int N, int K,
                 const float* __restrict__ bias, int reluOut, int reluA, int addC)
{
    __shared__ float As[64][17];
    __shared__ float Bs[16][64];
    int m0 = blockIdx.y * 64;
    int n0 = blockIdx.x * 64;
    int tid = threadIdx.x;
    int ty = tid >> 4;
    int tx = tid & 15;
    unsigned long long acc2[8][2];
#pragma unroll
    for (int i = 0; i < 8; i++) {
        acc2[i][0] = 0ULL; acc2[i][1] = 0ULL;
    }

    for (int k0 = 0; k0 < K; k0 += 16) {
#pragma unroll
        for (int r = 0; r < 8; r++) {
            int t = tid + r*128;
            int m = t >> 4, k = t & 15;
            int gm = m0 + m, gk = k0 + k;
            float v = (gm < M && gk < K) ? A[(size_t)gm*K + gk] : 0.f;
            if (reluA) v = fmaxf(v, 0.f);
            As[m][k] = v;
        }
#pragma unroll
        for (int r = 0; r < 8; r++) {
            int t = tid + r*128;
            int k = t >> 6;
            int n = t & 63;
            int gk = k0 + k, gn = n0 + n;
            Bs[k][n] = (gk < K && gn < N) ? B[(size_t)gk*N + gn] : 0.f;
        }
        __syncthreads();
#pragma unroll
        for (int kk = 0; kk < 16; kk++) {
            float4 bq = *(const float4*)&Bs[kk][tx*4];
            unsigned long long bb0, bb1;
            PACK2(bb0, bq.x, bq.y);
            PACK2(bb1, bq.z, bq.w);
#pragma unroll
            for (int i = 0; i < 8; i++) {
                float av = As[ty*8 + i][kk];
                unsigned long long aa;
                PACK2(aa, av, av);
                FMA2(acc2[i][0], aa, bb0);
                FMA2(acc2[i][1], aa, bb1);
            }
        }
        __syncthreads();
    }
#pragma unroll
    for (int i = 0; i < 8; i++) {
        int gm = m0 + ty*8 + i;
        if (gm >= M) continue;
        float v[4];
        UNPACK2(v[0], v[1], acc2[i][0]);
        UNPACK2(v[2], v[3], acc2[i][1]);
#pragma unroll
        for (int j = 0; j < 4; j++) {
            int gn = n0 + tx*4 + j;
            if (gn >= N) continue;
            float val = v[j];
            if (bias) val += bias[gn];
            if (addC) val += C[(size_t)gm*N + gn];
            if (reluOut) val = fmaxf(val, 0.f);
            C[(size_t)gm*N + gn] = val;
        }
    }
}

// ---------------- fp32 split-K GEMM with implicit 3x3 im2col, FFMA2 ----------------
template<int C, int RELU>
__global__ __launch_bounds__(128)
void gemm_splitk_i3_kernel(const float* __restrict__ in, const float* __restrict__ B,
                           float* __restrict__ Cpart, int N, int Kc)
{
    __shared__ float As[64][17];
    __shared__ float Bs[16][64];
    const int M = POS2;
    const int K = 9*C;
    const int SH = (C == 128) ? 7 : 6;
    int m0 = blockIdx.y * 64;
    int n0 = blockIdx.x * 64;
    int s  = blockIdx.z;
    int kbeg = s * Kc;
    int kend = kbeg + Kc; if (kend > K) kend = K;
    int tid = threadIdx.x;
    int ty = tid >> 4;
    int tx = tid & 15;
    unsigned long long acc2[8][2];
#pragma unroll
    for (int i = 0; i < 8; i++) {
        acc2[i][0] = 0ULL; acc2[i][1] = 0ULL;
    }

    for (int k0 = kbeg; k0 < kend; k0 += 16) {
#pragma unroll
        for (int r = 0; r < 8; r++) {
            int t = tid + r*128;
            int m = t >> 4, k = t & 15;
            int gm = m0 + m, gk = k0 + k;
            float v = 0.f;
            if (gm < M && gk < kend) {
                int ic = gk & (C - 1);
                int rr = gk >> SH;
                int kw = rr % 3, kh = rr / 3;
                int ow = gm % W2;
                int r2 = gm / W2;
                int oh = r2 % H2;
                int b  = r2 / H2;
                int ihh = oh + kh - 1, iww = ow + kw - 1;
                if (ihh >= 0 && ihh < H2 && iww >= 0 && iww < W2) {
                    v = in[((size_t)((b*H2 + ihh)*W2 + iww))*C + ic];
                    if (RELU) v = fmaxf(v, 0.f);
                }
            }
            As[m][k] = v;
        }
#pragma unroll
        for (int r = 0; r < 8; r++) {
            int t = tid + r*128;
            int k = t >> 6;
            int n = t & 63;
            int gk = k0 + k, gn = n0 + n;
            Bs[k][n] = (gk < kend && gn < N) ? B[(size_t)gk*N + gn] : 0.f;
        }
        __syncthreads();
#pragma unroll
        for (int kk = 0; kk < 16; kk++) {
            float4 bq = *(const float4*)&Bs[kk][tx*4];
            unsigned long long bb0, bb1;
            PACK2(bb0, bq.x, bq.y);
            PACK2(bb1, bq.z, bq.w);
#pragma unroll
            for (int i = 0; i < 8; i++) {
                float av = As[ty*8 + i][kk];
                unsigned long long aa;
                PACK2(aa, av, av);
                FMA2(acc2[i][0], aa, bb0);
                FMA2(acc2[i][1], aa, bb1);
            }
        }
        __syncthreads();
    }
    float* Cs = Cpart + (size_t)s * M * N;
#pragma unroll
    for (int i = 0; i < 8; i++) {
        int gm = m0 + ty*8 + i;
        if (gm >= M) continue;
        float v[4];
        UNPACK2(v[0], v[1], acc2[i][0]);
        UNPACK2(v[2], v[3], acc2[i][1]);
#pragma unroll
        for (int j = 0; j < 4; j++) {
            int gn = n0 + tx*4 + j;
            if (gn >= N) continue;
            Cs[(size_t)gm*N + gn] = v[j];
        }
    }
}

__global__ void reduce_splitk_kernel(const float* __restrict__ Cpart, float* __restrict__ C,
                                     int MN, int N, int S, const float* __restrict__ bias,
                                     int reluOut, int addC)
{
    int t = blockIdx.x * blockDim.x + threadIdx.x;
    if (t >= MN) return;
    float v = 0.f;
    for (int s = 0; s < S; s++) v += Cpart[(size_t)s*MN + t];
    if (bias) v += bias[t % N];
    if (addC) v += C[t];
    if (reluOut) v = fmaxf(v, 0.f);
    C[t] = v;
}

// ---------------- VQ ----------------
__global__ void vq_setup_kernel(const float* __restrict__ emb, float* __restrict__ esq,
                                int* __restrict__ counts, float* __restrict__ sqacc) {
    int k = threadIdx.x;
    float s = 0.f;
    const float* e = emb + k*64;
#pragma unroll
    for (int d = 0; d < 64; d++) s = fmaf(e[d], e[d], s);
    esq[k] = s;
    counts[k] = 0;
    if (k == 0) sqacc[0] = 0.f;
}

__global__ void vq_kernel(const float* __restrict__ z, const float* __restrict__ emb,
                          const float* __restrict__ esq, int* __restrict__ idx,
                          float* __restrict__ q, int* __restrict__ counts,
                          float* __restrict__ sqacc)
{
    __shared__ float zs[64];
    __shared__ float sb[128];
    __shared__ int   si[128];
    int pos = blockIdx.x;
    int tid = threadIdx.x;
    if (tid < 64) zs[tid] = z[pos*64 + tid];
    __syncthreads();
    float best = 3.4e38f; int bi = 0x7fffffff;
    for (int k = tid; k < KE; k += 128) {
        const float* e = emb + k*64;
        float dot = 0.f;
#pragma unroll
        for (int d = 0; d < 64; d++) dot = fmaf(e[d], zs[d], dot);
        float s = esq[k] - 2.f*dot;
        if (s < best || (s == best && k < bi)) { best = s; bi = k; }
    }
    sb[tid] = best; si[tid] = bi;
    __syncthreads();
    for (int off = 64; off > 0; off >>= 1) {
        if (tid < off) {
            float s2 = sb[tid+off]; int i2 = si[tid+off];
            if (s2 < sb[tid] || (s2 == sb[tid] && i2 < si[tid])) { sb[tid] = s2; si[tid] = i2; }
        }
        __syncthreads();
    }
    int bk = si[0];
    if (tid == 0) { idx[pos] = bk; atomicAdd(&counts[bk], 1); }
    __syncthreads();
    float v = 0.f;
    if (tid < 64) {
        float qv = emb[bk*64 + tid];
        q[pos*64 + tid] = qv;
        float d = qv - zs[tid];
        v = d*d;
    }
    sb[tid] = v;
    __syncthreads();
    for (int off = 64; off > 0; off >>= 1) {
        if (tid < off) sb[tid] += sb[tid+off];
        __syncthreads();
    }
    if (tid == 0) atomicAdd(sqacc, sb[0]);
}

__global__ void finalize_kernel(const int* __restrict__ counts, const float* __restrict__ sqacc,
                                float* __restrict__ out, long outN) {
    __shared__ float sh[512];
    int tid = threadIdx.x;
    float p = (float)counts[tid] / 960.f;
    sh[tid] = p * logf(p + 1e-10f);
    __syncthreads();
    for (int off = 256; off > 0; off >>= 1) {
        if (tid < off) sh[tid] += sh[tid+off];
        __syncthreads();
    }
    if (tid == 0) {
        out[0] = 1.25f * sqacc[0] / (float)(POS2*64);
        out[outN-1] = expf(-sh[0]);
    }
}

// ---------------- convT gathers ----------------
__global__ void gather_t1_kernel(const float* __restrict__ Y1, const float* __restrict__ bias,
                                 float* __restrict__ t1) {
    int t = blockIdx.x * blockDim.x + threadIdx.x;
    if (t >= POSD*16) return;
    int oc = (t & 15) * 4;
    int pos = t >> 4;
    int ow = pos % TW; int r = pos / TW;
    int oh = r % TH; int b = r / TH;
    float4 acc = *(const float4*)(bias + oc);
    int lo = oh - 10;
    int ih_lo = lo <= 0 ? 0 : (lo + 9)/10;
    int ih_hi = (oh + 1)/10; if (ih_hi > 4) ih_hi = 4;
    int lw = ow - 10;
    int iw_lo = lw <= 0 ? 0 : (lw + 9)/10;
    int iw_hi = (ow + 1)/10; if (iw_hi > 5) iw_hi = 5;
    for (int ih = ih_lo; ih <= ih_hi; ih++) {
        int kh = oh + 1 - 10*ih;
        for (int iw = iw_lo; iw <= iw_hi; iw++) {
            int kw = ow + 1 - 10*iw;
            float4 y = *(const float4*)(Y1 + (size_t)((b*5 + ih)*6 + iw)*NT1 + (kh*12 + kw)*64 + oc);
            acc.x += y.x; acc.y += y.y; acc.z += y.z; acc.w += y.w;
        }
    }
    acc.x = fmaxf(acc.x, 0.f); acc.y = fmaxf(acc.y, 0.f);
    acc.z = fmaxf(acc.z, 0.f); acc.w = fmaxf(acc.w, 0.f);
    *(float4*)(t1 + (size_t)pos*64 + oc) = acc;
}

// gather_recon v2: block per (b, oh); stage contributing Y2 rows in smem.
__global__ __launch_bounds__(128)
void gather_recon2_kernel(const float* __restrict__ Y2, const float* __restrict__ bias,
                          float* __restrict__ out)
{
    __shared__ float s[2][1320];
    int blk = blockIdx.x;
    int oh = blk % OHH;
    int b  = blk / OHH;
    int lo = oh - 8;
    int ih_lo = lo <= 0 ? 0 : (lo + 7)/8;
    int ih_hi = (oh + 1)/8; if (ih_hi > TH-1) ih_hi = TH-1;
    int nih = ih_hi - ih_lo + 1;
    int tid = threadIdx.x;
    for (int i = 0; i < nih; i++) {
        int ih = ih_lo + i;
        int kh = oh + 1 - 8*ih;
        const float* src = Y2 + (size_t)((b*TH + ih)*TW)*NT2 + kh*22;
        for (int t = tid; t < 1320; t += 128) {
            int c = t / 22, o = t % 22;
            s[i][t] = src[(size_t)c*NT2 + o];
        }
    }
    __syncthreads();
    float b0 = bias[0], b1 = bias[1];
    for (int t = tid; t < 2*OWW; t += 128) {
        int ow = t % OWW;
        int oc = t / OWW;
        int lw = ow - 9;
        int iw_lo = lw <= 0 ? 0 : (lw + 8)/9;
        int iw_hi = (ow + 1)/9; if (iw_hi > TW-1) iw_hi = TW-1;
        float acc = oc ? b1 : b0;
        for (int i = 0; i < nih; i++)
            for (int iw = iw_lo; iw <= iw_hi; iw++) {
                int kw = ow + 1 - 9*iw;
                acc += s[i][iw*22 + kw*2 + oc];
            }
        out[(((size_t)(b*2 + oc))*OHH + oh)*OWW + ow] = acc;
    }
}

// ---------------- host ----------------
static inline void launch_gemm128(const float* A, const float* B, float* C,
                                  int M, int N, int K, const float* bias,
                                  int reluOut, int reluA) {
    dim3 grid((N + 63)/64, (M + 127)/128);
    gemm128_kernel<<<grid, 128>>>(A, B, C, M, N, K, bias, reluOut, reluA);
}

static inline void launch_gemm_tf32(const float* A, const float* B, float* C,
                                    int M, int N, int K, int reluA) {
    dim3 grid((N + 63)/64, (M + 127)/128);
    gemm_tf32_kernel<<<grid, 256>>>(A, B, C, M, N, K, reluA);
}

static inline void launch_gemm(const float* A, const float* B, float* C,
                               int M, int N, int K, const float* bias,
                               int reluOut, int reluA, int addC) {
    dim3 grid((N + 63)/64, (M + 63)/64);
    gemm_kernel<<<grid, 128>>>(A, B, C, M, N, K, bias, reluOut, reluA, addC);
}

template<int C, int RELU>
static inline void launch_i3_splitk(const float* in, const float* B, float* Cout, float* part,
                                    int N, int S, const float* bias, int reluOut, int addC) {
    int K = 9*C;
    int Kc = (K + S - 1) / S;
    Kc = ((Kc + 15) / 16) * 16;
    S  = (K + Kc - 1) / Kc;
    dim3 grid((N + 63)/64, (POS2 + 63)/64, S);
    gemm_splitk_i3_kernel<C, RELU><<<grid, 128>>>(in, B, part, N, Kc);
    int MN = POS2 * N;
    reduce_splitk_kernel<<<(MN + 255)/256, 256>>>(part, Cout, MN, N, S, bias, reluOut, addC);
}

extern "C" void kernel_launch(void* const* d_in, const int* in_sizes, int n_in,
                              void* d_out, int out_size) {
    const float* x       = (const float*)d_in[0];
    const float* enc_w1  = (const float*)d_in[1];
    const float* enc_b1  = (const float*)d_in[2];
    const float* enc_w2  = (const float*)d_in[3];
    const float* enc_b2  = (const float*)d_in[4];
    const float* enc_w3  = (const float*)d_in[5];
    const float* enc_b3  = (const float*)d_in[6];
    const float* enc_rw1 = (const float*)d_in[7];
    const float* enc_rw2 = (const float*)d_in[8];
    const float* pre_w   = (const float*)d_in[9];
    const float* pre_b   = (const float*)d_in[10];
    const float* emb     = (const float*)d_in[11];
    const float* dec_w1  = (const float*)d_in[12];
    const float* dec_b1  = (const float*)d_in[13];
    const float* dec_rw1 = (const float*)d_in[14];
    const float* dec_rw2 = (const float*)d_in[15];
    const float* dec_tw1 = (const float*)d_in[16];
    const float* dec_tb1 = (const float*)d_in[17];
    const float* dec_tw2 = (const float*)d_in[18];
    const float* dec_tb2 = (const float*)d_in[19];
    float* out = (float*)d_out;

    float *p_A1, *p_h1, *p_col, *p_hA, *p_hB, *p_t64, *p_z, *p_q, *p_part;
    float *p_Y1, *p_t1, *p_Y2;
    float *p_w1t, *p_w2t, *p_w3t, *p_er1t, *p_er2t, *p_pret, *p_d1t, *p_dr1t, *p_dr2t;
    float *p_tw1t, *p_tw2t, *p_esq, *p_sqacc;
    int *p_counts, *p_idx;
    cudaGetSymbolAddress((void**)&p_A1, g_A1);
    cudaGetSymbolAddress((void**)&p_h1, g_h1);
    cudaGetSymbolAddress((void**)&p_col, g_col);
    cudaGetSymbolAddress((void**)&p_hA, g_hA);
    cudaGetSymbolAddress((void**)&p_hB, g_hB);
    cudaGetSymbolAddress((void**)&p_t64, g_t64);
    cudaGetSymbolAddress((void**)&p_z, g_z);
    cudaGetSymbolAddress((void**)&p_q, g_q);
    cudaGetSymbolAddress((void**)&p_part, g_part);
    cudaGetSymbolAddress((void**)&p_Y1, g_Y1);
    cudaGetSymbolAddress((void**)&p_t1, g_t1);
    cudaGetSymbolAddress((void**)&p_Y2, g_Y2);
    cudaGetSymbolAddress((void**)&p_w1t, g_w1t);
    cudaGetSymbolAddress((void**)&p_w2t, g_w2t);
    cudaGetSymbolAddress((void**)&p_w3t, g_w3t);
    cudaGetSymbolAddress((void**)&p_er1t, g_er1t);
    cudaGetSymbolAddress((void**)&p_er2t, g_er2t);
    cudaGetSymbolAddress((void**)&p_pret, g_pret);
    cudaGetSymbolAddress((void**)&p_d1t, g_d1t);
    cudaGetSymbolAddress((void**)&p_dr1t, g_dr1t);
    cudaGetSymbolAddress((void**)&p_dr2t, g_dr2t);
    cudaGetSymbolAddress((void**)&p_tw1t, g_tw1t);
    cudaGetSymbolAddress((void**)&p_tw2t, g_tw2t);
    cudaGetSymbolAddress((void**)&p_esq, g_esq);
    cudaGetSymbolAddress((void**)&p_sqacc, g_sqacc);
    cudaGetSymbolAddress((void**)&p_counts, g_counts);
    cudaGetSymbolAddress((void**)&p_idx, g_idx);

    // ---- ONE merged weight-transpose kernel ----
    {
        TJobs J;
        int j = 0;
        long off = 0;
        auto add = [&](const float* s, float* d, int co, int ci, int kh, int kw, int isT) {
            J.src[j] = s; J.dst[j] = d;
            J.cout[j] = co; J.cin[j] = ci; J.kh[j] = kh; J.kw[j] = kw; J.isT[j] = isT;
            J.off[j] = off;
            off += (long)co*ci*kh*kw;
            j++;
        };
        add(enc_w1,            p_w1t,            64, 2,  10, 11, 0);
        add(enc_w2,            p_w2t,            128,64, 12, 12, 0);
        add(enc_w3,            p_w3t,            128,128, 3,  3, 0);
        add(enc_rw1,           p_er1t,            64,128, 3,  3, 0);
        add(enc_rw1 + 73728,   p_er1t + 73728,    64,128, 3,  3, 0);
        add(enc_rw2,           p_er2t,           128, 64, 1,  1, 0);
        add(enc_rw2 + 8192,    p_er2t + 8192,    128, 64, 1,  1, 0);
        add(pre_w,             p_pret,            64,128, 1,  1, 0);
        add(dec_w1,            p_d1t,            128, 64, 3,  3, 0);
        add(dec_rw1,           p_dr1t,            64,128, 3,  3, 0);
        add(dec_rw1 + 73728,   p_dr1t + 73728,    64,128, 3,  3, 0);
        add(dec_rw2,           p_dr2t,           128, 64, 1,  1, 0);
        add(dec_rw2 + 8192,    p_dr2t + 8192,    128, 64, 1,  1, 0);
        add(dec_tw1,           p_tw1t,            64,128, 12, 12, 1);
        add(dec_tw2,           p_tw2t,             2, 64, 10, 11, 1);
        J.off[NJOBS] = off;
        long blocks = (off + 255)/256;
        wtrans_all_kernel<<<(unsigned)blocks, 256>>>(J);
    }

    // ---- encoder (fp32-accurate; safe for VQ argmin) ----
    {
        int total2 = POS1 * (K1/2);
        im2col_c1_kernel<<<(total2 + 255)/256, 256>>>(x, p_A1);
    }
    launch_gemm128(p_A1, p_w1t, p_h1, POS1, OC1, K1, enc_b1, 1, 0);

    // conv2: explicit im2col + 3xTF32 split-K (S=16)
    {
        int total4 = POS2 * 12*12*16;
        im2col4_c2_kernel<<<(total4 + 255)/256, 256>>>(p_h1, p_col);
        int S = 16;
        int Kc = K2 / S;
        dim3 grid(2, (POS2 + 127)/128, S);
        gemm3x_kernel<<<grid, 256>>>(p_col, p_w2t, p_part, POS2, 128, K2, Kc);
        int MN = POS2 * 128;
        reduce_splitk_kernel<<<(MN + 255)/256, 256>>>(p_part, p_hA, MN, 128, S, enc_b2, 1, 0);
    }

    // conv3 (implicit 3x3)
    launch_i3_splitk<128, 0>(p_hA, p_w3t, p_hB, p_part, 128, 8, enc_b3, 0, 0);

    for (int i = 0; i < 2; i++) {    // enc res stack
        launch_i3_splitk<128, 1>(p_hB, p_er1t + i*1152*64, p_t64, p_part, 64, 8, 0, 1, 0);
        launch_gemm(p_t64, p_er2t + i*64*128, p_hB, POS2, 128, 64, 0, 0, 0, 1);
    }
    launch_gemm(p_hB, p_pret, p_z, POS2, 64, 128, pre_b, 0, 1, 0);

    // ---- VQ ----
    vq_setup_kernel<<<1, KE>>>(emb, p_esq, p_counts, p_sqacc);
    vq_kernel<<<POS2, 128>>>(p_z, emb, p_esq, p_idx, p_q, p_counts, p_sqacc);
    finalize_kernel<<<1, KE>>>(p_counts, p_sqacc, out, (long)out_size);

    // ---- decoder ----
    launch_i3_splitk<64, 0>(p_q, p_d1t, p_hA, p_part, 128, 4, dec_b1, 0, 0);

    for (int i = 0; i < 2; i++) {    // dec res stack
        launch_i3_splitk<128, 1>(p_hA, p_dr1t + i*1152*64, p_t64, p_part, 64, 8, 0, 1, 0);
        launch_gemm(p_t64, p_dr2t + i*64*128, p_hA, POS2, 128, 64, 0, 0, 0, 1);
    }

    // convT1: tf32 GEMM (relu on input) + gather (+bias, relu)
    launch_gemm_tf32(p_hA, p_tw1t, p_Y1, POS2, NT1, 128, 1);
    gather_t1_kernel<<<(POSD*16 + 255)/256, 256>>>(p_Y1, dec_tb1, p_t1);

    // convT2: tf32 GEMM + smem-staged gather (+bias) -> recon at out+1
    launch_gemm_tf32(p_t1, p_tw2t, p_Y2, POSD, NT2, 64, 0);
    gather_recon2_kernel<<<NB*OHH, 128>>>(p_Y2, dec_tb2, out + 1);
}